// round 6
// baseline (speedup 1.0000x reference)
#include <cuda_runtime.h>

// Problem constants (MResConvPoint): B=4, C_IN=C_OUT=64, N=100000, K=6
#define NPTS   100000
#define NBATCH 4
#define KNBR   6
#define TPTS   32          // points per tile
#define BNEPS  1e-5f

// ---------------- scratch (device globals; no allocation allowed) ----------
__device__ float g_xT  [(size_t)NBATCH * NPTS * 64]; // x transposed  [B][N][64]
__device__ float g_rT  [(size_t)NBATCH * NPTS * 64]; // relu(h) transposed [B][N][64]
__device__ float g_hres[(size_t)NBATCH * 64 * NPTS]; // conv1 output (residual) [B][64][N]
__device__ float g_W0t [128 * 64];                   // W0 reshaped [s*64+c][o]
__device__ float g_W1t [128 * 64];                   // W1 * a[c] folded, same layout
__device__ float g_bias[64];                         // folded BN bias per output
__device__ float g_sum [64];                         // per-channel sum of relu(h)
__device__ float g_sumsq[64];                        // per-channel sumsq of relu(h)

// ---------------- K0: reshape W0, zero stat accumulators -------------------
__global__ void prep1_kernel(const float* __restrict__ W0) {
    const int t = threadIdx.x;
    if (t < 64) { g_sum[t] = 0.f; g_sumsq[t] = 0.f; }
    for (int i = t; i < 128 * 64; i += 256) {
        const int c128 = i >> 6, o = i & 63;
        const int s = c128 >> 6, c = c128 & 63;
        g_W0t[i] = W0[((o * 64) + c) * 2 + s];
    }
}

// ---------------- K1: transpose x [B][64][N] -> g_xT [B][N][64] ------------
__global__ void transpose_kernel(const float* __restrict__ x) {
    __shared__ float tile[32][33];
    const int b  = blockIdx.z;
    const int c0 = blockIdx.y * 32;
    const int n0 = blockIdx.x * 32;
    const int tx = threadIdx.x, ty = threadIdx.y;
    #pragma unroll
    for (int i = 0; i < 32; i += 8)
        tile[ty + i][tx] = x[((size_t)b * 64 + c0 + ty + i) * NPTS + n0 + tx];
    __syncthreads();
    #pragma unroll
    for (int i = 0; i < 32; i += 8)
        g_xT[((size_t)b * NPTS + n0 + ty + i) * 64 + c0 + tx] = tile[tx][ty + i];
}

// ---------------- K3: BN stats -> fold into W1 + bias ----------------------
__global__ void prep2_kernel(const float* __restrict__ W1,
                             const float* __restrict__ gamma,
                             const float* __restrict__ beta) {
    __shared__ float sa[64], sb[64];
    const int t = threadIdx.x;
    const float cnt = (float)((size_t)NBATCH * NPTS);
    if (t < 64) {
        const float mean = g_sum[t] / cnt;
        const float var  = g_sumsq[t] / cnt - mean * mean;
        const float a    = gamma[t] * rsqrtf(var + BNEPS);
        sa[t] = a;
        sb[t] = beta[t] - mean * a;
    }
    __syncthreads();
    for (int i = t; i < 128 * 64; i += 256) {
        const int c128 = i >> 6, o = i & 63;
        const int s = c128 >> 6, c = c128 & 63;
        g_W1t[i] = W1[((o * 64) + c) * 2 + s] * sa[c];
    }
    if (t < 64) {
        float acc = 0.f;
        #pragma unroll
        for (int c = 0; c < 64; c++)
            acc += sb[c] * (W1[((t * 64) + c) * 2 + 0] +
                            (float)KNBR * W1[((t * 64) + c) * 2 + 1]);
        g_bias[t] = acc;
    }
}

// ---------------- K2 / K4: fused gather + 64x32 GEMM -----------------------
// FIRST=true : src = g_xT, W = g_W0t; writes g_hres (+relu stats) and g_rT.
// FIRST=false: src = g_rT, W = g_W1t (BN-folded); out = relu(gemm + bias + hres).
template <bool FIRST>
__global__ __launch_bounds__(256)
void conv_kernel(const int* __restrict__ neigh, float* __restrict__ final_out) {
    __shared__ float sW[64 * 64];     // one 64-channel half of the weights
    __shared__ float sG[128 * 33];    // gathered [center(64); nbsum(64)] x 32 pts
    __shared__ float sH[64 * 33];     // output staging 64 x 32

    const float* __restrict__ src = FIRST ? g_xT  : g_rT;
    const float* __restrict__ Wt  = FIRST ? g_W0t : g_W1t;

    const int t  = threadIdx.x;
    const int b  = blockIdx.y;
    const int n0 = blockIdx.x * TPTS;

    // ---- gather phase: 8 threads per point, 8 channels (2 float4) each ----
    const int p  = t >> 3;
    const int g  = t & 7;
    const int n  = n0 + p;
    const int cb = g * 8;
    const float* base = src + (size_t)b * NPTS * 64;
    const float* crow = base + (size_t)n * 64 + cb;
    float4 c0 = *(const float4*)(crow);
    float4 c1 = *(const float4*)(crow + 4);
    float4 s0 = make_float4(0.f, 0.f, 0.f, 0.f);
    float4 s1 = make_float4(0.f, 0.f, 0.f, 0.f);
    const int* nb = neigh + ((size_t)b * NPTS + n) * KNBR;
    #pragma unroll
    for (int k = 0; k < KNBR; k++) {
        const float* r = base + (size_t)nb[k] * 64 + cb;
        const float4 a0 = *(const float4*)(r);
        const float4 a1 = *(const float4*)(r + 4);
        s0.x += a0.x; s0.y += a0.y; s0.z += a0.z; s0.w += a0.w;
        s1.x += a1.x; s1.y += a1.y; s1.z += a1.z; s1.w += a1.w;
    }
    sG[(cb + 0) * 33 + p] = c0.x; sG[(cb + 1) * 33 + p] = c0.y;
    sG[(cb + 2) * 33 + p] = c0.z; sG[(cb + 3) * 33 + p] = c0.w;
    sG[(cb + 4) * 33 + p] = c1.x; sG[(cb + 5) * 33 + p] = c1.y;
    sG[(cb + 6) * 33 + p] = c1.z; sG[(cb + 7) * 33 + p] = c1.w;
    sG[(64 + cb + 0) * 33 + p] = s0.x; sG[(64 + cb + 1) * 33 + p] = s0.y;
    sG[(64 + cb + 2) * 33 + p] = s0.z; sG[(64 + cb + 3) * 33 + p] = s0.w;
    sG[(64 + cb + 4) * 33 + p] = s1.x; sG[(64 + cb + 5) * 33 + p] = s1.y;
    sG[(64 + cb + 6) * 33 + p] = s1.z; sG[(64 + cb + 7) * 33 + p] = s1.w;

    // ---- GEMM: 64 outputs x 32 points, 128-channel reduction in 2 halves --
    const int ob = (t & 15) * 4;     // 4 output channels
    const int pb = (t >> 4) * 2;     // 2 points
    float a00, a01, a10, a11, a20, a21, a30, a31;
    if (FIRST) {
        a00 = a01 = a10 = a11 = a20 = a21 = a30 = a31 = 0.f;
    } else {
        a00 = g_bias[ob + 0]; a01 = a00;
        a10 = g_bias[ob + 1]; a11 = a10;
        a20 = g_bias[ob + 2]; a21 = a20;
        a30 = g_bias[ob + 3]; a31 = a30;
    }
    for (int half = 0; half < 2; half++) {
        __syncthreads();  // half0: gather done; half1: prev sW reads done
        {
            const float4* wsrc = (const float4*)(Wt + half * 64 * 64);
            float4* wdst = (float4*)sW;
            #pragma unroll
            for (int i = t; i < 64 * 64 / 4; i += 256) wdst[i] = wsrc[i];
        }
        __syncthreads();
        const float* gbase = &sG[(half * 64) * 33];
        #pragma unroll 8
        for (int c = 0; c < 64; c++) {
            const float4 w  = *(const float4*)&sW[c * 64 + ob];
            const float g0 = gbase[c * 33 + pb];
            const float g1 = gbase[c * 33 + pb + 1];
            a00 += w.x * g0; a01 += w.x * g1;
            a10 += w.y * g0; a11 += w.y * g1;
            a20 += w.z * g0; a21 += w.z * g1;
            a30 += w.w * g0; a31 += w.w * g1;
        }
    }

    // ---- stage to smem for coalesced output -------------------------------
    sH[(ob + 0) * 33 + pb] = a00; sH[(ob + 0) * 33 + pb + 1] = a01;
    sH[(ob + 1) * 33 + pb] = a10; sH[(ob + 1) * 33 + pb + 1] = a11;
    sH[(ob + 2) * 33 + pb] = a20; sH[(ob + 2) * 33 + pb + 1] = a21;
    sH[(ob + 3) * 33 + pb] = a30; sH[(ob + 3) * 33 + pb + 1] = a31;
    __syncthreads();

    const int w    = t >> 5;
    const int lane = t & 31;
    if (FIRST) {
        // residual write [B][O][N] (coalesced) + per-channel relu stats
        #pragma unroll
        for (int r = 0; r < 8; r++) {
            const int o = w * 8 + r;
            const float v = sH[o * 33 + lane];
            g_hres[((size_t)b * 64 + o) * NPTS + n0 + lane] = v;
            const float rv = fmaxf(v, 0.f);
            float s = rv, sq = rv * rv;
            #pragma unroll
            for (int off = 16; off; off >>= 1) {
                s  += __shfl_down_sync(0xffffffffu, s,  off);
                sq += __shfl_down_sync(0xffffffffu, sq, off);
            }
            if (lane == 0) { atomicAdd(&g_sum[o], s); atomicAdd(&g_sumsq[o], sq); }
        }
        // relu(h) transposed [B][N][64] (coalesced float4 rows) for conv2 gather
        float4 r0, r1;
        r0.x = fmaxf(sH[(cb + 0) * 33 + p], 0.f);
        r0.y = fmaxf(sH[(cb + 1) * 33 + p], 0.f);
        r0.z = fmaxf(sH[(cb + 2) * 33 + p], 0.f);
        r0.w = fmaxf(sH[(cb + 3) * 33 + p], 0.f);
        r1.x = fmaxf(sH[(cb + 4) * 33 + p], 0.f);
        r1.y = fmaxf(sH[(cb + 5) * 33 + p], 0.f);
        r1.z = fmaxf(sH[(cb + 6) * 33 + p], 0.f);
        r1.w = fmaxf(sH[(cb + 7) * 33 + p], 0.f);
        float* dst = g_rT + ((size_t)b * NPTS + n) * 64 + cb;
        *(float4*)(dst)     = r0;
        *(float4*)(dst + 4) = r1;
    } else {
        // out = relu(gemm + bias + residual), coalesced [B][O][N]
        #pragma unroll
        for (int r = 0; r < 8; r++) {
            const int o = w * 8 + r;
            const size_t idx = ((size_t)b * 64 + o) * NPTS + n0 + lane;
            const float v = sH[o * 33 + lane] + g_hres[idx];
            final_out[idx] = fmaxf(v, 0.f);
        }
    }
}

// ---------------------------------------------------------------------------
extern "C" void kernel_launch(void* const* d_in, const int* in_sizes, int n_in,
                              void* d_out, int out_size) {
    const float* x     = (const float*)d_in[0];
    const int*   neigh = (const int*)  d_in[1];
    const float* W0    = (const float*)d_in[2];
    const float* W1    = (const float*)d_in[3];
    const float* gamma = (const float*)d_in[4];
    const float* beta  = (const float*)d_in[5];
    float* out = (float*)d_out;

    prep1_kernel<<<1, 256>>>(W0);

    dim3 tgrid(NPTS / 32, 2, NBATCH);
    transpose_kernel<<<tgrid, dim3(32, 8)>>>(x);

    dim3 cgrid(NPTS / TPTS, NBATCH);
    conv_kernel<true><<<cgrid, 256>>>(neigh, nullptr);

    prep2_kernel<<<1, 256>>>(W1, gamma, beta);

    conv_kernel<false><<<cgrid, 256>>>(neigh, out);
}

// round 14
// speedup vs baseline: 1.0308x; 1.0308x over previous
#include <cuda_runtime.h>

// Problem constants (MResConvPoint): B=4, C_IN=C_OUT=64, N=100000, K=6
#define NPTS   100000
#define NBATCH 4
#define KNBR   6
#define TPTS   32          // points per tile
#define BNEPS  1e-5f

typedef unsigned long long u64;

// packed f32x2 helpers (sm_100+; ptxas never auto-fuses these)
#define FMA2(acc, a, b) \
    asm("fma.rn.f32x2 %0, %1, %2, %0;" : "+l"(acc) : "l"(a), "l"(b))
#define PACK2(d, lo, hi) \
    asm("mov.b64 %0, {%1, %2};" : "=l"(d) : "r"(lo), "r"(hi))
#define UNPACK2(lo, hi, in) \
    asm("mov.b64 {%0, %1}, %2;" : "=r"(lo), "=r"(hi) : "l"(in))

// ---------------- scratch (device globals; no allocation allowed) ----------
__device__ float g_xT  [(size_t)NBATCH * NPTS * 64]; // x transposed  [B][N][64]
__device__ float g_rT  [(size_t)NBATCH * NPTS * 64]; // relu(h) transposed [B][N][64]
__device__ float g_hres[(size_t)NBATCH * 64 * NPTS]; // conv1 output (residual) [B][64][N]
__device__ float g_W0t [128 * 64];                   // W0 reshaped [s*64+c][o]
__device__ float g_W1t [128 * 64];                   // W1 * a[c] folded, same layout
__device__ float g_bias[64];                         // folded BN bias per output
__device__ float g_sum [64];                         // per-channel sum of relu(h)
__device__ float g_sumsq[64];                        // per-channel sumsq of relu(h)

// ---------------- K1: transpose x [B][64][N] -> g_xT [B][N][64] ------------
// Block (0,0,0) additionally does the prep1 work (W0 reshape + stat zeroing);
// it runs concurrently with the other transpose blocks.
__global__ void transpose_kernel(const float* __restrict__ x,
                                 const float* __restrict__ W0) {
    __shared__ float tile[32][33];
    const int b  = blockIdx.z;
    const int c0 = blockIdx.y * 32;
    const int n0 = blockIdx.x * 32;
    const int tx = threadIdx.x, ty = threadIdx.y;
    #pragma unroll
    for (int i = 0; i < 32; i += 8)
        tile[ty + i][tx] = x[((size_t)b * 64 + c0 + ty + i) * NPTS + n0 + tx];
    __syncthreads();
    #pragma unroll
    for (int i = 0; i < 32; i += 8)
        g_xT[((size_t)b * NPTS + n0 + ty + i) * 64 + c0 + tx] = tile[tx][ty + i];

    if (blockIdx.x == 0 && blockIdx.y == 0 && blockIdx.z == 0) {
        const int t = ty * 32 + tx;   // 0..255
        if (t < 64) { g_sum[t] = 0.f; g_sumsq[t] = 0.f; }
        for (int i = t; i < 128 * 64; i += 256) {
            const int c128 = i >> 6, o = i & 63;
            const int s = c128 >> 6, c = c128 & 63;
            g_W0t[i] = W0[((o * 64) + c) * 2 + s];
        }
    }
}

// ---------------- K3: BN stats -> fold into W1 + bias (9 blocks) -----------
__global__ void prep2_kernel(const float* __restrict__ W1,
                             const float* __restrict__ gamma,
                             const float* __restrict__ beta) {
    __shared__ float sa[64], sb[64];
    const int t = threadIdx.x;
    const float cnt = (float)((size_t)NBATCH * NPTS);
    if (t < 64) {
        const float mean = g_sum[t] / cnt;
        const float var  = g_sumsq[t] / cnt - mean * mean;
        const float a    = gamma[t] * rsqrtf(var + BNEPS);
        sa[t] = a;
        sb[t] = beta[t] - mean * a;
    }
    __syncthreads();
    const int blk = blockIdx.x;
    if (blk < 8) {
        // each of 8 blocks folds 1024 of the 8192 W1t elements
        for (int i = blk * 1024 + t; i < (blk + 1) * 1024; i += 256) {
            const int c128 = i >> 6, o = i & 63;
            const int s = c128 >> 6, c = c128 & 63;
            g_W1t[i] = W1[((o * 64) + c) * 2 + s] * sa[c];
        }
    } else if (t < 64) {
        float acc = 0.f;
        #pragma unroll
        for (int c = 0; c < 64; c++)
            acc += sb[c] * (W1[((t * 64) + c) * 2 + 0] +
                            (float)KNBR * W1[((t * 64) + c) * 2 + 1]);
        g_bias[t] = acc;
    }
}

// ---------------- K2 / K4: fused gather + 64x32 GEMM (f32x2 packed) --------
// FIRST=true : src = g_xT, W = g_W0t; writes g_hres (+relu stats) and g_rT.
// FIRST=false: src = g_rT, W = g_W1t (BN-folded); out = relu(gemm + bias + hres).
template <bool FIRST>
__global__ __launch_bounds__(256)
void conv_kernel(const int* __restrict__ neigh, float* __restrict__ final_out) {
    __shared__ __align__(16) float sW[64 * 64];  // one 64-channel half of weights
    __shared__ __align__(16) float sG[128 * 33]; // [center(64); nbsum(64)] x 32 pts
    __shared__ __align__(16) float sH[64 * 33];  // output staging 64 x 32

    const float* __restrict__ src = FIRST ? g_xT  : g_rT;
    const float* __restrict__ Wt  = FIRST ? g_W0t : g_W1t;

    const int t  = threadIdx.x;
    const int b  = blockIdx.y;
    const int n0 = blockIdx.x * TPTS;

    // ---- gather phase: 8 threads per point, 8 channels (2 float4) each ----
    const int p  = t >> 3;
    const int g  = t & 7;
    const int n  = n0 + p;
    const int cb = g * 8;
    const float* base = src + (size_t)b * NPTS * 64;
    const float* crow = base + (size_t)n * 64 + cb;
    float4 c0 = *(const float4*)(crow);
    float4 c1 = *(const float4*)(crow + 4);
    float4 s0 = make_float4(0.f, 0.f, 0.f, 0.f);
    float4 s1 = make_float4(0.f, 0.f, 0.f, 0.f);
    // 24B-stride rows are 8B aligned -> 3x LDG.64 for the 6 indices
    const int2* nb2 = (const int2*)(neigh + ((size_t)b * NPTS + n) * KNBR);
    const int2 q0 = nb2[0], q1 = nb2[1], q2 = nb2[2];
    const int idx6[KNBR] = {q0.x, q0.y, q1.x, q1.y, q2.x, q2.y};
    #pragma unroll
    for (int k = 0; k < KNBR; k++) {
        const float* r = base + (size_t)idx6[k] * 64 + cb;
        const float4 a0 = *(const float4*)(r);
        const float4 a1 = *(const float4*)(r + 4);
        s0.x += a0.x; s0.y += a0.y; s0.z += a0.z; s0.w += a0.w;
        s1.x += a1.x; s1.y += a1.y; s1.z += a1.z; s1.w += a1.w;
    }
    sG[(cb + 0) * 33 + p] = c0.x; sG[(cb + 1) * 33 + p] = c0.y;
    sG[(cb + 2) * 33 + p] = c0.z; sG[(cb + 3) * 33 + p] = c0.w;
    sG[(cb + 4) * 33 + p] = c1.x; sG[(cb + 5) * 33 + p] = c1.y;
    sG[(cb + 6) * 33 + p] = c1.z; sG[(cb + 7) * 33 + p] = c1.w;
    sG[(64 + cb + 0) * 33 + p] = s0.x; sG[(64 + cb + 1) * 33 + p] = s0.y;
    sG[(64 + cb + 2) * 33 + p] = s0.z; sG[(64 + cb + 3) * 33 + p] = s0.w;
    sG[(64 + cb + 4) * 33 + p] = s1.x; sG[(64 + cb + 5) * 33 + p] = s1.y;
    sG[(64 + cb + 6) * 33 + p] = s1.z; sG[(64 + cb + 7) * 33 + p] = s1.w;

    // ---- GEMM: 64 outputs x 32 points, packed f32x2 over output pairs -----
    const int ob = (t & 15) * 4;     // 4 output channels
    const int pb = (t >> 4) * 2;     // 2 points
    // A* = point pb, B* = point pb+1; each u64 = (out ob+0,ob+1) or (ob+2,ob+3)
    u64 A0, A1, B0, B1;
    if (FIRST) {
        A0 = A1 = B0 = B1 = 0ull;    // (0.0f, 0.0f)
    } else {
        u64 b01, b23;
        PACK2(b01, __float_as_uint(g_bias[ob + 0]), __float_as_uint(g_bias[ob + 1]));
        PACK2(b23, __float_as_uint(g_bias[ob + 2]), __float_as_uint(g_bias[ob + 3]));
        A0 = b01; A1 = b23; B0 = b01; B1 = b23;
    }
    for (int half = 0; half < 2; half++) {
        __syncthreads();  // half0: gather done; half1: prev sW reads done
        {
            const float4* wsrc = (const float4*)(Wt + half * 64 * 64);
            float4* wdst = (float4*)sW;
            #pragma unroll
            for (int i = t; i < 64 * 64 / 4; i += 256) wdst[i] = wsrc[i];
        }
        __syncthreads();
        const float* gbase = &sG[(half * 64) * 33];
        #pragma unroll 8
        for (int c = 0; c < 64; c++) {
            const ulonglong2 w = *(const ulonglong2*)&sW[c * 64 + ob]; // (w0,w1),(w2,w3)
            const float g0 = gbase[c * 33 + pb];
            const float g1 = gbase[c * 33 + pb + 1];
            u64 G0, G1;
            PACK2(G0, __float_as_uint(g0), __float_as_uint(g0));
            PACK2(G1, __float_as_uint(g1), __float_as_uint(g1));
            FMA2(A0, w.x, G0); FMA2(A1, w.y, G0);
            FMA2(B0, w.x, G1); FMA2(B1, w.y, G1);
        }
    }

    // ---- unpack + stage to smem for coalesced output ----------------------
    {
        unsigned int lo, hi;
        UNPACK2(lo, hi, A0);
        sH[(ob + 0) * 33 + pb] = __uint_as_float(lo);
        sH[(ob + 1) * 33 + pb] = __uint_as_float(hi);
        UNPACK2(lo, hi, A1);
        sH[(ob + 2) * 33 + pb] = __uint_as_float(lo);
        sH[(ob + 3) * 33 + pb] = __uint_as_float(hi);
        UNPACK2(lo, hi, B0);
        sH[(ob + 0) * 33 + pb + 1] = __uint_as_float(lo);
        sH[(ob + 1) * 33 + pb + 1] = __uint_as_float(hi);
        UNPACK2(lo, hi, B1);
        sH[(ob + 2) * 33 + pb + 1] = __uint_as_float(lo);
        sH[(ob + 3) * 33 + pb + 1] = __uint_as_float(hi);
    }
    __syncthreads();

    const int w    = t >> 5;
    const int lane = t & 31;
    if (FIRST) {
        // residual write [B][O][N] (coalesced) + per-channel relu stats
        #pragma unroll
        for (int r = 0; r < 8; r++) {
            const int o = w * 8 + r;
            const float v = sH[o * 33 + lane];
            g_hres[((size_t)b * 64 + o) * NPTS + n0 + lane] = v;
            const float rv = fmaxf(v, 0.f);
            float s = rv, sq = rv * rv;
            #pragma unroll
            for (int off = 16; off; off >>= 1) {
                s  += __shfl_down_sync(0xffffffffu, s,  off);
                sq += __shfl_down_sync(0xffffffffu, sq, off);
            }
            if (lane == 0) { atomicAdd(&g_sum[o], s); atomicAdd(&g_sumsq[o], sq); }
        }
        // relu(h) transposed [B][N][64] (coalesced float4 rows) for conv2 gather
        float4 r0, r1;
        r0.x = fmaxf(sH[(cb + 0) * 33 + p], 0.f);
        r0.y = fmaxf(sH[(cb + 1) * 33 + p], 0.f);
        r0.z = fmaxf(sH[(cb + 2) * 33 + p], 0.f);
        r0.w = fmaxf(sH[(cb + 3) * 33 + p], 0.f);
        r1.x = fmaxf(sH[(cb + 4) * 33 + p], 0.f);
        r1.y = fmaxf(sH[(cb + 5) * 33 + p], 0.f);
        r1.z = fmaxf(sH[(cb + 6) * 33 + p], 0.f);
        r1.w = fmaxf(sH[(cb + 7) * 33 + p], 0.f);
        float* dst = g_rT + ((size_t)b * NPTS + n) * 64 + cb;
        *(float4*)(dst)     = r0;
        *(float4*)(dst + 4) = r1;
    } else {
        // out = relu(gemm + bias + residual), coalesced [B][O][N]
        #pragma unroll
        for (int r = 0; r < 8; r++) {
            const int o = w * 8 + r;
            const size_t idx = ((size_t)b * 64 + o) * NPTS + n0 + lane;
            const float v = sH[o * 33 + lane] + g_hres[idx];
            final_out[idx] = fmaxf(v, 0.f);
        }
    }
}

// ---------------------------------------------------------------------------
extern "C" void kernel_launch(void* const* d_in, const int* in_sizes, int n_in,
                              void* d_out, int out_size) {
    const float* x     = (const float*)d_in[0];
    const int*   neigh = (const int*)  d_in[1];
    const float* W0    = (const float*)d_in[2];
    const float* W1    = (const float*)d_in[3];
    const float* gamma = (const float*)d_in[4];
    const float* beta  = (const float*)d_in[5];
    float* out = (float*)d_out;

    dim3 tgrid(NPTS / 32, 2, NBATCH);
    transpose_kernel<<<tgrid, dim3(32, 8)>>>(x, W0);   // includes prep1 work

    dim3 cgrid(NPTS / TPTS, NBATCH);
    conv_kernel<true><<<cgrid, 256>>>(neigh, nullptr);

    prep2_kernel<<<9, 256>>>(W1, gamma, beta);

    conv_kernel<false><<<cgrid, 256>>>(neigh, out);
}